// round 11
// baseline (speedup 1.0000x reference)
#include <cuda_runtime.h>
#include <math.h>

constexpr int B_  = 8;
constexpr int N_  = 512;
constexpr int M_  = 512;
constexpr int D_  = 512;
constexpr int ND_ = N_ + M_ - 1;   // 1023 anti-diagonals
constexpr float NEGL    = -1.0e9f;
constexpr float INV_LN2 = 1.44269504088896340736f;

// Diagonal-major scratch (zero-initialized; invalid slots are never written,
// so they stay zero — bwd relies on this for implicit masking).
__device__ float2 g_tha[(size_t)B_ * ND_ * N_];
__device__ float2 g_w  [(size_t)B_ * ND_ * N_];
__device__ float  g_e  [(size_t)B_ * ND_ * N_];

__device__ __forceinline__ float ex2f_(float x) { float y; asm("ex2.approx.ftz.f32 %0, %1;" : "=f"(y) : "f"(x)); return y; }
__device__ __forceinline__ float lg2f_(float x) { float y; asm("lg2.approx.f32 %0, %1;"     : "=f"(y) : "f"(x)); return y; }
__device__ __forceinline__ float rcpf_(float x) { float y; asm("rcp.approx.f32 %0, %1;"     : "=f"(y) : "f"(x)); return y; }

// extract float i (static after unroll) from a float4 window
#define WV_GET(wv, ii) ( ((ii) & 3) == 0 ? (wv)[(ii) >> 2].x \
                       : ((ii) & 3) == 1 ? (wv)[(ii) >> 2].y \
                       : ((ii) & 3) == 2 ? (wv)[(ii) >> 2].z \
                       :                   (wv)[(ii) >> 2].w )

// ---------------------------------------------------------------------------
// GEMM + activation (R1 SIMT version, known 120us): 128x128 tile, 256 thr,
// 8x8 micro tile, K-chunks of 16.
// ---------------------------------------------------------------------------
__global__ void __launch_bounds__(256, 2) gemm_act_kernel(
    const float* __restrict__ zx, const float* __restrict__ zy,
    const float* __restrict__ gx, const float* __restrict__ gy,
    float* __restrict__ out)
{
    const int mz  = blockIdx.z;
    const int b   = mz & 7;
    const int sel = mz >> 3;
    const float* X = (sel ? gx : zx) + (size_t)b * N_ * D_;
    const float* Y = (sel ? gy : zy) + (size_t)b * M_ * D_;
    float* C = out + (size_t)(1 + sel) * B_ * N_ * M_ + (size_t)b * N_ * M_;

    const int row0 = blockIdx.y * 128;
    const int col0 = blockIdx.x * 128;

    __shared__ float Xs[16][132];
    __shared__ float Ys[16][132];

    const int t  = threadIdx.x;
    const int lr = t >> 1;
    const int lk = (t & 1) * 8;
    const int ty = t >> 4;
    const int tx = t & 15;

    float acc[8][8];
#pragma unroll
    for (int r = 0; r < 8; ++r)
#pragma unroll
        for (int c = 0; c < 8; ++c) acc[r][c] = 0.f;

    for (int k0 = 0; k0 < D_; k0 += 16) {
        const float4 xv0 = *(const float4*)(X + (size_t)(row0 + lr) * D_ + k0 + lk);
        const float4 xv1 = *(const float4*)(X + (size_t)(row0 + lr) * D_ + k0 + lk + 4);
        const float4 yv0 = *(const float4*)(Y + (size_t)(col0 + lr) * D_ + k0 + lk);
        const float4 yv1 = *(const float4*)(Y + (size_t)(col0 + lr) * D_ + k0 + lk + 4);
        __syncthreads();
        Xs[lk + 0][lr] = xv0.x; Xs[lk + 1][lr] = xv0.y; Xs[lk + 2][lr] = xv0.z; Xs[lk + 3][lr] = xv0.w;
        Xs[lk + 4][lr] = xv1.x; Xs[lk + 5][lr] = xv1.y; Xs[lk + 6][lr] = xv1.z; Xs[lk + 7][lr] = xv1.w;
        Ys[lk + 0][lr] = yv0.x; Ys[lk + 1][lr] = yv0.y; Ys[lk + 2][lr] = yv0.z; Ys[lk + 3][lr] = yv0.w;
        Ys[lk + 4][lr] = yv1.x; Ys[lk + 5][lr] = yv1.y; Ys[lk + 6][lr] = yv1.z; Ys[lk + 7][lr] = yv1.w;
        __syncthreads();
#pragma unroll
        for (int kk = 0; kk < 16; ++kk) {
            float a0[8], b0[8];
            *(float4*)(a0)     = *(const float4*)&Xs[kk][ty * 8];
            *(float4*)(a0 + 4) = *(const float4*)&Xs[kk][ty * 8 + 4];
            *(float4*)(b0)     = *(const float4*)&Ys[kk][tx * 8];
            *(float4*)(b0 + 4) = *(const float4*)&Ys[kk][tx * 8 + 4];
#pragma unroll
            for (int r = 0; r < 8; ++r)
#pragma unroll
                for (int c = 0; c < 8; ++c)
                    acc[r][c] = fmaf(a0[r], b0[c], acc[r][c]);
        }
    }

#pragma unroll
    for (int r = 0; r < 8; ++r) {
        const int row = row0 + ty * 8 + r;
#pragma unroll
        for (int c4 = 0; c4 < 8; c4 += 4) {
            float4 v;
            float* vp = &v.x;
#pragma unroll
            for (int q = 0; q < 4; ++q) {
                const float x = acc[r][c4 + q];
                const float l = log1pf(__expf(-fabsf(x)));
                vp[q] = sel ? (fminf(x, 0.f) - l)     // log_sigmoid
                            : (fmaxf(x, 0.f) + l);    // softplus
            }
            *(float4*)(C + (size_t)row * M_ + col0 + tx * 8 + c4) = v;
        }
    }
}

// ---------------------------------------------------------------------------
// Diagonalize: theta,A (row-major) -> g_tha (diag-major float2, pre-scaled).
// ---------------------------------------------------------------------------
__global__ void __launch_bounds__(256) diag_kernel(const float* __restrict__ out)
{
    const float* theta = out + (size_t)B_ * N_ * M_;
    const float* Ag    = out + (size_t)2 * B_ * N_ * M_;
    const int b  = blockIdx.z;
    const int i0 = blockIdx.y * 32;
    const int j0 = blockIdx.x * 32;

    __shared__ float sth[32 * 32];
    __shared__ float sa [32 * 32];

    const int t    = threadIdx.x;
    const int warp = t >> 5;
    const int lane = t & 31;

#pragma unroll
    for (int it = 0; it < 4; ++it) {
        const int r = warp + it * 8;
        const int c = lane;
        const size_t g = ((size_t)b * N_ + (i0 + r)) * M_ + (j0 + c);
        sth[r * 32 + c] = theta[g] * INV_LN2;
        sa [r * 32 + c] = Ag[g]    * INV_LN2;
    }
    __syncthreads();

    float2* dst = g_tha + (size_t)b * ND_ * N_;
#pragma unroll
    for (int dd0 = 0; dd0 < 64; dd0 += 8) {
        const int dd = dd0 + warp;
        const int il = lane;
        const int jl = dd - il;
        if ((unsigned)jl < 32u) {
            const int d = i0 + j0 + dd;
            dst[(size_t)d * N_ + (i0 + il)] = make_float2(sth[il * 32 + jl], sa[il * 32 + jl]);
        }
    }
}

// ---------------------------------------------------------------------------
// Undiagonalize: g_e (diag-major) -> aln (row-major).
// ---------------------------------------------------------------------------
__global__ void __launch_bounds__(256) undiag_kernel(float* __restrict__ out)
{
    const int b  = blockIdx.z;
    const int i0 = blockIdx.y * 32;
    const int j0 = blockIdx.x * 32;

    __shared__ float se[32 * 32];

    const int t    = threadIdx.x;
    const int warp = t >> 5;
    const int lane = t & 31;

    const float* src = g_e + (size_t)b * ND_ * N_;
#pragma unroll
    for (int dd0 = 0; dd0 < 64; dd0 += 8) {
        const int dd = dd0 + warp;
        const int il = lane;
        const int jl = dd - il;
        if ((unsigned)jl < 32u) {
            const int d = i0 + j0 + dd;
            se[il * 32 + jl] = src[(size_t)d * N_ + (i0 + il)];
        }
    }
    __syncthreads();

    float* alnB = out + (size_t)b * N_ * M_;
#pragma unroll
    for (int it = 0; it < 4; ++it) {
        const int r = warp + it * 8;
        const int c = lane;
        alnB[(size_t)(i0 + r) * M_ + (j0 + c)] = se[r * 32 + c];
    }
}

// ---------------------------------------------------------------------------
// Forward soft-NW: tile wavefront; ring window bulk-prefetched into registers
// at chunk start (all values proven written >=1 barrier earlier), removing the
// per-step LDS. d0 = 32*(w+c) so d0-4 ≡ 0 (mod 4): aligned float4 window.
// ---------------------------------------------------------------------------
__global__ void __launch_bounds__(512) nw_fwd_kernel()
{
    const int b    = blockIdx.x;
    const int tid  = threadIdx.x;
    const int wid  = tid >> 5;
    const int lane = tid & 31;
    const int r    = tid;
    const int w0   = wid * 32;

    __shared__ float bndV[17][128];   // row 16 never written: NEGL boundary
    for (int i = tid; i < 17 * 128; i += 512) ((float*)bndV)[i] = NEGL;
    __syncthreads();

    const float2* THA = g_tha + (size_t)b * ND_ * N_;
    float2*       Wb  = g_w   + (size_t)b * ND_ * N_;

    float*        ringWr  = bndV[wid];
    const float4* ringRd4 = (const float4*)bndV[wid == 0 ? 16 : wid - 1];

    float2 th[16];
#pragma unroll
    for (int q = 0; q < 16; ++q) th[q] = THA[(size_t)(w0 + q) * N_ + r];

    float vp     = NEGL;
    float nbPrev = (tid == 0) ? 0.f : NEGL;   // seeds V[0,0] = 0 for cell (0,0)

    for (int t = 0; t < 47; ++t) {
        const int c = t - 2 * wid;
        if (c >= 0 && c < 17) {
            const int d0 = w0 + 32 * c;

            // bulk ring prefetch: window covers ring[d0-4 .. d0+31]
            float4 wv[9];
            const int blk0 = ((d0 - 4 + 256) & 127) >> 2;
#pragma unroll
            for (int k2 = 0; k2 < 9; ++k2) wv[k2] = ringRd4[(blk0 + k2) & 31];

#pragma unroll
            for (int s = 0; s < 32; ++s) {
                const int d = d0 + s;
                const float2 ta = th[s & 15];
                int dp = d + 16; dp = dp > ND_ - 1 ? ND_ - 1 : dp;
                th[s & 15] = THA[(size_t)dp * N_ + r];

                const float ringv = WV_GET(wv, 3 + s);        // ring[d-1]
                float nb = __shfl_up_sync(0xffffffffu, vp, 1);
                nb = (lane == 0) ? ringv : nb;

                const float x0 = ta.y + nb;        // A + V[i-1, j]
                const float x2 = ta.y + vp;        // A + V[i,   j-1]
                const float dg = nbPrev;           //     V[i-1, j-1]
                const float m  = fmaxf(fmaxf(x0, x2), dg);
                const float e0 = ex2f_(x0 - m);
                const float e1 = ex2f_(dg - m);
                const float e2 = ex2f_(x2 - m);
                const float ss = e0 + e1 + e2;
                const float rr = rcpf_(ss);
                const float v  = ta.x + m + lg2f_(ss);

                const bool active = (unsigned)(d - r) < (unsigned)M_;
                if (active) Wb[(size_t)d * N_ + r] = make_float2(e0 * rr, e2 * rr);
                vp = active ? v : vp;
                nbPrev = nb;
                if (lane == 31) ringWr[d & 127] = vp;          // @p STS.32
            }
        }
        __syncthreads();
    }
}

// ---------------------------------------------------------------------------
// Backward soft-NW: off-chain weights (two depth-8 diag-major register
// streams) + bulk ring window prefetch per chunk (8 x LDS.128; d0 ≡ 30 mod 32
// so d0-30 ≡ 0 mod 4: aligned). Serial chain = shfl(E) -> FMA -> SEL.
//   E[i,j] = E[i+1,j]*wU(i+1,j) + E[i,j+1]*wL(i,j+1) + E[i+1,j+1]*wD(i+1,j+1)
// ---------------------------------------------------------------------------
__global__ void __launch_bounds__(512) nw_bwd_kernel()
{
    const int b    = blockIdx.x;
    const int tid  = threadIdx.x;
    const int wid  = tid >> 5;
    const int lane = tid & 31;
    const int r    = tid;
    const int w0   = wid * 32;
    const int dTop = w0 + 542;
    const bool hasNext = (r + 1 < N_);   // row r+1 exists

    __shared__ float eRing[17][128];     // row 16 never written: zero boundary
    for (int i = tid; i < 17 * 128; i += 512) ((float*)eRing)[i] = 0.f;
    __syncthreads();

    const float2* Wb = g_w + (size_t)b * ND_ * N_;
    float*        Eb = g_e + (size_t)b * ND_ * N_;

    float*        ringWr  = eRing[wid];
    const float4* ringRd4 = (const float4*)eRing[wid + 1];   // warp 15 -> zeros

    const float2 zero2 = make_float2(0.f, 0.f);

    float2 qA[8], qB[8];
#pragma unroll
    for (int q = 0; q < 8; ++q) {
        const int dd = dTop + 1 - q;
        const bool ok = (dd <= ND_ - 1);
        qA[q] = ok ? Wb[(size_t)dd * N_ + r] : zero2;
        qB[q] = (ok && hasNext) ? Wb[(size_t)dd * N_ + r + 1] : zero2;
    }

    float2 bPrev = zero2;
    {
        const int dd = dTop + 2;
        if (dd <= ND_ - 1 && hasNext) bPrev = Wb[(size_t)dd * N_ + r + 1];
    }

    float ep      = 0.f;   // my E at d+1
    float nbEPrev = 0.f;   // neighbor E at d+2

    for (int t = 0; t < 47; ++t) {
        const int cc = t - 2 * (15 - wid);
        if (cc >= 0 && cc < 17) {
            const int d0 = dTop - 32 * cc;

            // bulk ring prefetch: window covers ring[d0-30 .. d0+1]
            float4 wv[8];
            const int blk0 = ((d0 - 30 + 256) & 127) >> 2;
#pragma unroll
            for (int k2 = 0; k2 < 8; ++k2) wv[k2] = ringRd4[(blk0 + k2) & 31];

#pragma unroll
            for (int s = 0; s < 32; ++s) {
                const int d = d0 - s;
                const float2 cA = qA[s & 7];    // W[d+1][r]
                const float2 cB = qB[s & 7];    // W[d+1][r+1]
                int dd = d - 7; dd = dd < 0 ? 0 : dd;
                qA[s & 7] = Wb[(size_t)dd * N_ + r];
                qB[s & 7] = hasNext ? Wb[(size_t)dd * N_ + r + 1] : zero2;

                const float rv = WV_GET(wv, 31 - s);         // ring[d+1]
                float nbE = __shfl_down_sync(0xffffffffu, ep, 1);
                nbE = (lane == 31) ? rv : nbE;

                float e = nbE * cB.x                          // E[i+1,j]   * wU
                        + ep  * cA.y                          // E[i,j+1]   * wL
                        + nbEPrev * (1.f - bPrev.x - bPrev.y);// E[i+1,j+1] * wD
                e = (d == 1022 && r == 511) ? 1.f : e;        // base case E[N,M]

                const bool active = (unsigned)(d - r) < (unsigned)M_;
                const float ev = active ? e : 0.f;
                Eb[(size_t)d * N_ + r] = ev;                  // unconditional STG
                ep = active ? e : ep;
                nbEPrev = nbE;
                bPrev = cB;
                if (lane == 0) ringWr[d & 127] = ep;          // @p STS.32
            }
        }
        __syncthreads();
    }
}

// ---------------------------------------------------------------------------
// launch
// ---------------------------------------------------------------------------
extern "C" void kernel_launch(void* const* d_in, const int* in_sizes, int n_in,
                              void* d_out, int out_size)
{
    const float* zx = (const float*)d_in[0];
    const float* zy = (const float*)d_in[1];
    const float* gx = (const float*)d_in[2];
    const float* gy = (const float*)d_in[3];
    float* out = (float*)d_out;   // [aln | theta | A]

    dim3 ggrid(M_ / 128, N_ / 128, 2 * B_);
    gemm_act_kernel<<<ggrid, 256>>>(zx, zy, gx, gy, out);

    dim3 tgrid(M_ / 32, N_ / 32, B_);
    diag_kernel<<<tgrid, 256>>>(out);
    nw_fwd_kernel<<<B_, 512>>>();
    nw_bwd_kernel<<<B_, 512>>>();
    undiag_kernel<<<tgrid, 256>>>(out);
}

// round 12
// speedup vs baseline: 1.0402x; 1.0402x over previous
#include <cuda_runtime.h>
#include <math.h>

constexpr int B_  = 8;
constexpr int N_  = 512;
constexpr int M_  = 512;
constexpr int D_  = 512;
constexpr int ND_ = N_ + M_ - 1;   // 1023 anti-diagonals
constexpr float NEGL    = -1.0e9f;
constexpr float INV_LN2 = 1.44269504088896340736f;

// Diagonal-major scratch (zero-initialized; invalid slots are never written,
// so they stay zero — bwd relies on this for implicit masking).
__device__ float2 g_tha[(size_t)B_ * ND_ * N_];
__device__ float2 g_w  [(size_t)B_ * ND_ * N_];
__device__ float  g_e  [(size_t)B_ * ND_ * N_];

__device__ __forceinline__ float ex2f_(float x) { float y; asm("ex2.approx.ftz.f32 %0, %1;" : "=f"(y) : "f"(x)); return y; }
__device__ __forceinline__ float lg2f_(float x) { float y; asm("lg2.approx.f32 %0, %1;"     : "=f"(y) : "f"(x)); return y; }
__device__ __forceinline__ float rcpf_(float x) { float y; asm("rcp.approx.f32 %0, %1;"     : "=f"(y) : "f"(x)); return y; }

// ---------------------------------------------------------------------------
// GEMM + activation (R1 SIMT version, known 120us): 128x128 tile, 256 thr,
// 8x8 micro tile, K-chunks of 16.
// ---------------------------------------------------------------------------
__global__ void __launch_bounds__(256, 2) gemm_act_kernel(
    const float* __restrict__ zx, const float* __restrict__ zy,
    const float* __restrict__ gx, const float* __restrict__ gy,
    float* __restrict__ out)
{
    const int mz  = blockIdx.z;
    const int b   = mz & 7;
    const int sel = mz >> 3;
    const float* X = (sel ? gx : zx) + (size_t)b * N_ * D_;
    const float* Y = (sel ? gy : zy) + (size_t)b * M_ * D_;
    float* C = out + (size_t)(1 + sel) * B_ * N_ * M_ + (size_t)b * N_ * M_;

    const int row0 = blockIdx.y * 128;
    const int col0 = blockIdx.x * 128;

    __shared__ float Xs[16][132];
    __shared__ float Ys[16][132];

    const int t  = threadIdx.x;
    const int lr = t >> 1;
    const int lk = (t & 1) * 8;
    const int ty = t >> 4;
    const int tx = t & 15;

    float acc[8][8];
#pragma unroll
    for (int r = 0; r < 8; ++r)
#pragma unroll
        for (int c = 0; c < 8; ++c) acc[r][c] = 0.f;

    for (int k0 = 0; k0 < D_; k0 += 16) {
        const float4 xv0 = *(const float4*)(X + (size_t)(row0 + lr) * D_ + k0 + lk);
        const float4 xv1 = *(const float4*)(X + (size_t)(row0 + lr) * D_ + k0 + lk + 4);
        const float4 yv0 = *(const float4*)(Y + (size_t)(col0 + lr) * D_ + k0 + lk);
        const float4 yv1 = *(const float4*)(Y + (size_t)(col0 + lr) * D_ + k0 + lk + 4);
        __syncthreads();
        Xs[lk + 0][lr] = xv0.x; Xs[lk + 1][lr] = xv0.y; Xs[lk + 2][lr] = xv0.z; Xs[lk + 3][lr] = xv0.w;
        Xs[lk + 4][lr] = xv1.x; Xs[lk + 5][lr] = xv1.y; Xs[lk + 6][lr] = xv1.z; Xs[lk + 7][lr] = xv1.w;
        Ys[lk + 0][lr] = yv0.x; Ys[lk + 1][lr] = yv0.y; Ys[lk + 2][lr] = yv0.z; Ys[lk + 3][lr] = yv0.w;
        Ys[lk + 4][lr] = yv1.x; Ys[lk + 5][lr] = yv1.y; Ys[lk + 6][lr] = yv1.z; Ys[lk + 7][lr] = yv1.w;
        __syncthreads();
#pragma unroll
        for (int kk = 0; kk < 16; ++kk) {
            float a0[8], b0[8];
            *(float4*)(a0)     = *(const float4*)&Xs[kk][ty * 8];
            *(float4*)(a0 + 4) = *(const float4*)&Xs[kk][ty * 8 + 4];
            *(float4*)(b0)     = *(const float4*)&Ys[kk][tx * 8];
            *(float4*)(b0 + 4) = *(const float4*)&Ys[kk][tx * 8 + 4];
#pragma unroll
            for (int r = 0; r < 8; ++r)
#pragma unroll
                for (int c = 0; c < 8; ++c)
                    acc[r][c] = fmaf(a0[r], b0[c], acc[r][c]);
        }
    }

#pragma unroll
    for (int r = 0; r < 8; ++r) {
        const int row = row0 + ty * 8 + r;
#pragma unroll
        for (int c4 = 0; c4 < 8; c4 += 4) {
            float4 v;
            float* vp = &v.x;
#pragma unroll
            for (int q = 0; q < 4; ++q) {
                const float x = acc[r][c4 + q];
                const float l = log1pf(__expf(-fabsf(x)));
                vp[q] = sel ? (fminf(x, 0.f) - l)     // log_sigmoid
                            : (fmaxf(x, 0.f) + l);    // softplus
            }
            *(float4*)(C + (size_t)row * M_ + col0 + tx * 8 + c4) = v;
        }
    }
}

// ---------------------------------------------------------------------------
// Diagonalize: theta,A (row-major) -> g_tha (diag-major float2, pre-scaled).
// ---------------------------------------------------------------------------
__global__ void __launch_bounds__(256) diag_kernel(const float* __restrict__ out)
{
    const float* theta = out + (size_t)B_ * N_ * M_;
    const float* Ag    = out + (size_t)2 * B_ * N_ * M_;
    const int b  = blockIdx.z;
    const int i0 = blockIdx.y * 32;
    const int j0 = blockIdx.x * 32;

    __shared__ float sth[32 * 32];
    __shared__ float sa [32 * 32];

    const int t    = threadIdx.x;
    const int warp = t >> 5;
    const int lane = t & 31;

#pragma unroll
    for (int it = 0; it < 4; ++it) {
        const int r = warp + it * 8;
        const int c = lane;
        const size_t g = ((size_t)b * N_ + (i0 + r)) * M_ + (j0 + c);
        sth[r * 32 + c] = theta[g] * INV_LN2;
        sa [r * 32 + c] = Ag[g]    * INV_LN2;
    }
    __syncthreads();

    float2* dst = g_tha + (size_t)b * ND_ * N_;
#pragma unroll
    for (int dd0 = 0; dd0 < 64; dd0 += 8) {
        const int dd = dd0 + warp;
        const int il = lane;
        const int jl = dd - il;
        if ((unsigned)jl < 32u) {
            const int d = i0 + j0 + dd;
            dst[(size_t)d * N_ + (i0 + il)] = make_float2(sth[il * 32 + jl], sa[il * 32 + jl]);
        }
    }
}

// ---------------------------------------------------------------------------
// Undiagonalize: g_e (diag-major) -> aln (row-major).
// ---------------------------------------------------------------------------
__global__ void __launch_bounds__(256) undiag_kernel(float* __restrict__ out)
{
    const int b  = blockIdx.z;
    const int i0 = blockIdx.y * 32;
    const int j0 = blockIdx.x * 32;

    __shared__ float se[32 * 32];

    const int t    = threadIdx.x;
    const int warp = t >> 5;
    const int lane = t & 31;

    const float* src = g_e + (size_t)b * ND_ * N_;
#pragma unroll
    for (int dd0 = 0; dd0 < 64; dd0 += 8) {
        const int dd = dd0 + warp;
        const int il = lane;
        const int jl = dd - il;
        if ((unsigned)jl < 32u) {
            const int d = i0 + j0 + dd;
            se[il * 32 + jl] = src[(size_t)d * N_ + (i0 + il)];
        }
    }
    __syncthreads();

    float* alnB = out + (size_t)b * N_ * M_;
#pragma unroll
    for (int it = 0; it < 4; ++it) {
        const int r = warp + it * 8;
        const int c = lane;
        alnB[(size_t)(i0 + r) * M_ + (j0 + c)] = se[r * 32 + c];
    }
}

// ---------------------------------------------------------------------------
// Forward soft-NW: R7 step body, rescheduled as C=16 chunks with skew 3.
// 79 waves x 16 steps = 1264 wall slots (was 47x32 = 1504).
// ---------------------------------------------------------------------------
__global__ void __launch_bounds__(512) nw_fwd_kernel()
{
    const int b    = blockIdx.x;
    const int tid  = threadIdx.x;
    const int wid  = tid >> 5;
    const int lane = tid & 31;
    const int r    = tid;
    const int w0   = wid * 32;

    __shared__ float bndV[17][128];   // row 16 never written: NEGL boundary
    for (int i = tid; i < 17 * 128; i += 512) ((float*)bndV)[i] = NEGL;
    __syncthreads();

    const float2* THA = g_tha + (size_t)b * ND_ * N_;
    float2*       Wb  = g_w   + (size_t)b * ND_ * N_;

    float*       ringWr = bndV[wid];
    const float* ringRd = bndV[wid == 0 ? 16 : wid - 1];

    float2 th[16];
#pragma unroll
    for (int q = 0; q < 16; ++q) th[q] = THA[(size_t)(w0 + q) * N_ + r];

    float vp     = NEGL;
    float nbPrev = (tid == 0) ? 0.f : NEGL;   // seeds V[0,0] = 0 for cell (0,0)

    for (int t = 0; t < 79; ++t) {
        const int c = t - 3 * wid;
        if (c >= 0 && c < 34) {
            const int d0 = w0 + 16 * c;
#pragma unroll
            for (int s = 0; s < 16; ++s) {
                const int d = d0 + s;
                const float2 ta = th[s & 15];
                int dp = d + 16; dp = dp > ND_ - 1 ? ND_ - 1 : dp;
                th[s & 15] = THA[(size_t)dp * N_ + r];

                const float ringv = ringRd[(d - 1) & 127];     // broadcast LDS
                float nb = __shfl_up_sync(0xffffffffu, vp, 1);
                nb = (lane == 0) ? ringv : nb;

                const float x0 = ta.y + nb;        // A + V[i-1, j]
                const float x2 = ta.y + vp;        // A + V[i,   j-1]
                const float dg = nbPrev;           //     V[i-1, j-1]
                const float m  = fmaxf(fmaxf(x0, x2), dg);
                const float e0 = ex2f_(x0 - m);
                const float e1 = ex2f_(dg - m);
                const float e2 = ex2f_(x2 - m);
                const float ss = e0 + e1 + e2;
                const float rr = rcpf_(ss);
                const float v  = ta.x + m + lg2f_(ss);

                const bool active = (unsigned)(d - r) < (unsigned)M_;
                if (active) Wb[(size_t)d * N_ + r] = make_float2(e0 * rr, e2 * rr);
                vp = active ? v : vp;
                nbPrev = nb;
                if (lane == 31) ringWr[d & 127] = vp;          // @p STS.32
            }
        }
        __syncthreads();
    }
}

// ---------------------------------------------------------------------------
// Backward soft-NW: R7 step body (off-chain weights via two depth-16
// diag-major register streams), rescheduled as C=16 chunks with skew 3.
//   E[i,j] = E[i+1,j]*wU(i+1,j) + E[i,j+1]*wL(i,j+1) + E[i+1,j+1]*wD(i+1,j+1)
// ---------------------------------------------------------------------------
__global__ void __launch_bounds__(512) nw_bwd_kernel()
{
    const int b    = blockIdx.x;
    const int tid  = threadIdx.x;
    const int wid  = tid >> 5;
    const int lane = tid & 31;
    const int r    = tid;
    const int w0   = wid * 32;
    const int dTop = w0 + 542;
    const bool hasNext = (r + 1 < N_);   // row r+1 exists

    __shared__ float eRing[17][128];     // row 16 never written: zero boundary
    for (int i = tid; i < 17 * 128; i += 512) ((float*)eRing)[i] = 0.f;
    __syncthreads();

    const float2* Wb = g_w + (size_t)b * ND_ * N_;
    float*        Eb = g_e + (size_t)b * ND_ * N_;

    float*       ringWr = eRing[wid];
    const float* ringRd = eRing[wid + 1];   // warp 15 -> row 16 (zeros)

    const float2 zero2 = make_float2(0.f, 0.f);

    float2 qA[16], qB[16];
#pragma unroll
    for (int q = 0; q < 16; ++q) {
        const int dd = dTop + 1 - q;
        const bool ok = (dd <= ND_ - 1);
        qA[q] = ok ? Wb[(size_t)dd * N_ + r] : zero2;
        qB[q] = (ok && hasNext) ? Wb[(size_t)dd * N_ + r + 1] : zero2;
    }

    float2 bPrev = zero2;
    {
        const int dd = dTop + 2;
        if (dd <= ND_ - 1 && hasNext) bPrev = Wb[(size_t)dd * N_ + r + 1];
    }

    float ep      = 0.f;   // my E at d+1
    float nbEPrev = 0.f;   // neighbor E at d+2

    for (int t = 0; t < 79; ++t) {
        const int cc = t - 3 * (15 - wid);
        if (cc >= 0 && cc < 34) {
            const int d0 = dTop - 16 * cc;
#pragma unroll
            for (int s = 0; s < 16; ++s) {
                const int d = d0 - s;
                const float2 cA = qA[s & 15];    // W[d+1][r]
                const float2 cB = qB[s & 15];    // W[d+1][r+1]
                int dd = d - 15; dd = dd < 0 ? 0 : dd;
                qA[s & 15] = Wb[(size_t)dd * N_ + r];
                qB[s & 15] = hasNext ? Wb[(size_t)dd * N_ + r + 1] : zero2;

                const float rv = ringRd[(d + 1) & 127];     // broadcast LDS
                float nbE = __shfl_down_sync(0xffffffffu, ep, 1);
                nbE = (lane == 31) ? rv : nbE;

                float e = nbE * cB.x                          // E[i+1,j]   * wU
                        + ep  * cA.y                          // E[i,j+1]   * wL
                        + nbEPrev * (1.f - bPrev.x - bPrev.y);// E[i+1,j+1] * wD
                e = (d == 1022 && r == 511) ? 1.f : e;        // base case E[N,M]

                const bool active = (unsigned)(d - r) < (unsigned)M_;
                const float ev = active ? e : 0.f;
                Eb[(size_t)d * N_ + r] = ev;                  // unconditional STG
                ep = active ? e : ep;
                nbEPrev = nbE;
                bPrev = cB;
                if (lane == 0) ringWr[d & 127] = ep;          // @p STS.32
            }
        }
        __syncthreads();
    }
}

// ---------------------------------------------------------------------------
// launch
// ---------------------------------------------------------------------------
extern "C" void kernel_launch(void* const* d_in, const int* in_sizes, int n_in,
                              void* d_out, int out_size)
{
    const float* zx = (const float*)d_in[0];
    const float* zy = (const float*)d_in[1];
    const float* gx = (const float*)d_in[2];
    const float* gy = (const float*)d_in[3];
    float* out = (float*)d_out;   // [aln | theta | A]

    dim3 ggrid(M_ / 128, N_ / 128, 2 * B_);
    gemm_act_kernel<<<ggrid, 256>>>(zx, zy, gx, gy, out);

    dim3 tgrid(M_ / 32, N_ / 32, B_);
    diag_kernel<<<tgrid, 256>>>(out);
    nw_fwd_kernel<<<B_, 512>>>();
    nw_bwd_kernel<<<B_, 512>>>();
    undiag_kernel<<<tgrid, 256>>>(out);
}

// round 13
// speedup vs baseline: 1.1153x; 1.0721x over previous
#include <cuda_runtime.h>
#include <math.h>

constexpr int B_  = 8;
constexpr int N_  = 512;
constexpr int M_  = 512;
constexpr int D_  = 512;
constexpr int ND_ = N_ + M_ - 1;   // 1023 anti-diagonals
constexpr float NEGL    = -1.0e9f;
constexpr float INV_LN2 = 1.44269504088896340736f;

// Diagonal-major scratch (zero-initialized; invalid slots are never written,
// so they stay zero — bwd relies on this for implicit masking).
__device__ float2 g_tha[(size_t)B_ * ND_ * N_];
__device__ float2 g_w  [(size_t)B_ * ND_ * N_];
__device__ float  g_e  [(size_t)B_ * ND_ * N_];

__device__ __forceinline__ float ex2f_(float x) { float y; asm("ex2.approx.ftz.f32 %0, %1;" : "=f"(y) : "f"(x)); return y; }
__device__ __forceinline__ float lg2f_(float x) { float y; asm("lg2.approx.f32 %0, %1;"     : "=f"(y) : "f"(x)); return y; }
__device__ __forceinline__ float rcpf_(float x) { float y; asm("rcp.approx.f32 %0, %1;"     : "=f"(y) : "f"(x)); return y; }

// named barrier, 64 threads (one producer warp + one consumer warp)
__device__ __forceinline__ void nbar_(int id) {
    asm volatile("bar.sync %0, 64;" :: "r"(id) : "memory");
}

// ---------------------------------------------------------------------------
// GEMM + activation (R1 SIMT version, known 120us): 128x128 tile, 256 thr,
// 8x8 micro tile, K-chunks of 16.
// ---------------------------------------------------------------------------
__global__ void __launch_bounds__(256, 2) gemm_act_kernel(
    const float* __restrict__ zx, const float* __restrict__ zy,
    const float* __restrict__ gx, const float* __restrict__ gy,
    float* __restrict__ out)
{
    const int mz  = blockIdx.z;
    const int b   = mz & 7;
    const int sel = mz >> 3;
    const float* X = (sel ? gx : zx) + (size_t)b * N_ * D_;
    const float* Y = (sel ? gy : zy) + (size_t)b * M_ * D_;
    float* C = out + (size_t)(1 + sel) * B_ * N_ * M_ + (size_t)b * N_ * M_;

    const int row0 = blockIdx.y * 128;
    const int col0 = blockIdx.x * 128;

    __shared__ float Xs[16][132];
    __shared__ float Ys[16][132];

    const int t  = threadIdx.x;
    const int lr = t >> 1;
    const int lk = (t & 1) * 8;
    const int ty = t >> 4;
    const int tx = t & 15;

    float acc[8][8];
#pragma unroll
    for (int r = 0; r < 8; ++r)
#pragma unroll
        for (int c = 0; c < 8; ++c) acc[r][c] = 0.f;

    for (int k0 = 0; k0 < D_; k0 += 16) {
        const float4 xv0 = *(const float4*)(X + (size_t)(row0 + lr) * D_ + k0 + lk);
        const float4 xv1 = *(const float4*)(X + (size_t)(row0 + lr) * D_ + k0 + lk + 4);
        const float4 yv0 = *(const float4*)(Y + (size_t)(col0 + lr) * D_ + k0 + lk);
        const float4 yv1 = *(const float4*)(Y + (size_t)(col0 + lr) * D_ + k0 + lk + 4);
        __syncthreads();
        Xs[lk + 0][lr] = xv0.x; Xs[lk + 1][lr] = xv0.y; Xs[lk + 2][lr] = xv0.z; Xs[lk + 3][lr] = xv0.w;
        Xs[lk + 4][lr] = xv1.x; Xs[lk + 5][lr] = xv1.y; Xs[lk + 6][lr] = xv1.z; Xs[lk + 7][lr] = xv1.w;
        Ys[lk + 0][lr] = yv0.x; Ys[lk + 1][lr] = yv0.y; Ys[lk + 2][lr] = yv0.z; Ys[lk + 3][lr] = yv0.w;
        Ys[lk + 4][lr] = yv1.x; Ys[lk + 5][lr] = yv1.y; Ys[lk + 6][lr] = yv1.z; Ys[lk + 7][lr] = yv1.w;
        __syncthreads();
#pragma unroll
        for (int kk = 0; kk < 16; ++kk) {
            float a0[8], b0[8];
            *(float4*)(a0)     = *(const float4*)&Xs[kk][ty * 8];
            *(float4*)(a0 + 4) = *(const float4*)&Xs[kk][ty * 8 + 4];
            *(float4*)(b0)     = *(const float4*)&Ys[kk][tx * 8];
            *(float4*)(b0 + 4) = *(const float4*)&Ys[kk][tx * 8 + 4];
#pragma unroll
            for (int r = 0; r < 8; ++r)
#pragma unroll
                for (int c = 0; c < 8; ++c)
                    acc[r][c] = fmaf(a0[r], b0[c], acc[r][c]);
        }
    }

#pragma unroll
    for (int r = 0; r < 8; ++r) {
        const int row = row0 + ty * 8 + r;
#pragma unroll
        for (int c4 = 0; c4 < 8; c4 += 4) {
            float4 v;
            float* vp = &v.x;
#pragma unroll
            for (int q = 0; q < 4; ++q) {
                const float x = acc[r][c4 + q];
                const float l = log1pf(__expf(-fabsf(x)));
                vp[q] = sel ? (fminf(x, 0.f) - l)     // log_sigmoid
                            : (fmaxf(x, 0.f) + l);    // softplus
            }
            *(float4*)(C + (size_t)row * M_ + col0 + tx * 8 + c4) = v;
        }
    }
}

// ---------------------------------------------------------------------------
// Diagonalize: theta,A (row-major) -> g_tha (diag-major float2, pre-scaled).
// ---------------------------------------------------------------------------
__global__ void __launch_bounds__(256) diag_kernel(const float* __restrict__ out)
{
    const float* theta = out + (size_t)B_ * N_ * M_;
    const float* Ag    = out + (size_t)2 * B_ * N_ * M_;
    const int b  = blockIdx.z;
    const int i0 = blockIdx.y * 32;
    const int j0 = blockIdx.x * 32;

    __shared__ float sth[32 * 32];
    __shared__ float sa [32 * 32];

    const int t    = threadIdx.x;
    const int warp = t >> 5;
    const int lane = t & 31;

#pragma unroll
    for (int it = 0; it < 4; ++it) {
        const int r = warp + it * 8;
        const int c = lane;
        const size_t g = ((size_t)b * N_ + (i0 + r)) * M_ + (j0 + c);
        sth[r * 32 + c] = theta[g] * INV_LN2;
        sa [r * 32 + c] = Ag[g]    * INV_LN2;
    }
    __syncthreads();

    float2* dst = g_tha + (size_t)b * ND_ * N_;
#pragma unroll
    for (int dd0 = 0; dd0 < 64; dd0 += 8) {
        const int dd = dd0 + warp;
        const int il = lane;
        const int jl = dd - il;
        if ((unsigned)jl < 32u) {
            const int d = i0 + j0 + dd;
            dst[(size_t)d * N_ + (i0 + il)] = make_float2(sth[il * 32 + jl], sa[il * 32 + jl]);
        }
    }
}

// ---------------------------------------------------------------------------
// Undiagonalize: g_e (diag-major) -> aln (row-major).
// ---------------------------------------------------------------------------
__global__ void __launch_bounds__(256) undiag_kernel(float* __restrict__ out)
{
    const int b  = blockIdx.z;
    const int i0 = blockIdx.y * 32;
    const int j0 = blockIdx.x * 32;

    __shared__ float se[32 * 32];

    const int t    = threadIdx.x;
    const int warp = t >> 5;
    const int lane = t & 31;

    const float* src = g_e + (size_t)b * ND_ * N_;
#pragma unroll
    for (int dd0 = 0; dd0 < 64; dd0 += 8) {
        const int dd = dd0 + warp;
        const int il = lane;
        const int jl = dd - il;
        if ((unsigned)jl < 32u) {
            const int d = i0 + j0 + dd;
            se[il * 32 + jl] = src[(size_t)d * N_ + (i0 + il)];
        }
    }
    __syncthreads();

    float* alnB = out + (size_t)b * N_ * M_;
#pragma unroll
    for (int it = 0; it < 4; ++it) {
        const int r = warp + it * 8;
        const int c = lane;
        alnB[(size_t)(i0 + r) * M_ + (j0 + c)] = se[r * 32 + c];
    }
}

// ---------------------------------------------------------------------------
// Forward soft-NW: R7 step body, decoupled warps via pairwise named barriers.
// Warp w consumer-syncs on bar id=w before each chunk; producer-syncs on
// bar id=w+1 after chunks 1..16 plus one extra (17 phases each side).
// Consumer start #c pairs with producer end after chunk c+1; producer lead
// bounded at 2 chunks (~65 < 128 ring slots).
// ---------------------------------------------------------------------------
__global__ void __launch_bounds__(512) nw_fwd_kernel()
{
    const int b    = blockIdx.x;
    const int tid  = threadIdx.x;
    const int wid  = tid >> 5;
    const int lane = tid & 31;
    const int r    = tid;
    const int w0   = wid * 32;

    __shared__ float bndV[17][128];   // row 16 never written: NEGL boundary
    for (int i = tid; i < 17 * 128; i += 512) ((float*)bndV)[i] = NEGL;
    __syncthreads();

    const float2* THA = g_tha + (size_t)b * ND_ * N_;
    float2*       Wb  = g_w   + (size_t)b * ND_ * N_;

    float*       ringWr = bndV[wid];
    const float* ringRd = bndV[wid == 0 ? 16 : wid - 1];

    float2 th[16];
#pragma unroll
    for (int q = 0; q < 16; ++q) th[q] = THA[(size_t)(w0 + q) * N_ + r];

    float vp     = NEGL;
    float nbPrev = (tid == 0) ? 0.f : NEGL;   // seeds V[0,0] = 0 for cell (0,0)

    for (int c = 0; c < 17; ++c) {
        if (wid > 0) nbar_(wid);              // wait producer through chunk c+1
        const int d0 = w0 + 32 * c;
#pragma unroll
        for (int s = 0; s < 32; ++s) {
            const int d = d0 + s;
            const float2 ta = th[s & 15];
            int dp = d + 16; dp = dp > ND_ - 1 ? ND_ - 1 : dp;
            th[s & 15] = THA[(size_t)dp * N_ + r];

            const float ringv = ringRd[(d - 1) & 127];     // broadcast LDS
            float nb = __shfl_up_sync(0xffffffffu, vp, 1);
            nb = (lane == 0) ? ringv : nb;

            const float x0 = ta.y + nb;        // A + V[i-1, j]
            const float x2 = ta.y + vp;        // A + V[i,   j-1]
            const float dg = nbPrev;           //     V[i-1, j-1]
            const float m  = fmaxf(fmaxf(x0, x2), dg);
            const float e0 = ex2f_(x0 - m);
            const float e1 = ex2f_(dg - m);
            const float e2 = ex2f_(x2 - m);
            const float ss = e0 + e1 + e2;
            const float rr = rcpf_(ss);
            const float v  = ta.x + m + lg2f_(ss);

            const bool active = (unsigned)(d - r) < (unsigned)M_;
            if (active) Wb[(size_t)d * N_ + r] = make_float2(e0 * rr, e2 * rr);
            vp = active ? v : vp;
            nbPrev = nb;
            if (lane == 31) ringWr[d & 127] = vp;          // @p STS.32
        }
        if (wid < 15 && c >= 1) nbar_(wid + 1);   // signal: chunk c done
    }
    if (wid < 15) nbar_(wid + 1);                 // extra phase (balance 17/17)
}

// ---------------------------------------------------------------------------
// Backward soft-NW: R7 step body (off-chain weights via two depth-16
// diag-major register streams), decoupled warps via pairwise named barriers.
// Pair id k (1..15): producer = warp k, consumer = warp k-1.
//   E[i,j] = E[i+1,j]*wU(i+1,j) + E[i,j+1]*wL(i,j+1) + E[i+1,j+1]*wD(i+1,j+1)
// ---------------------------------------------------------------------------
__global__ void __launch_bounds__(512) nw_bwd_kernel()
{
    const int b    = blockIdx.x;
    const int tid  = threadIdx.x;
    const int wid  = tid >> 5;
    const int lane = tid & 31;
    const int r    = tid;
    const int w0   = wid * 32;
    const int dTop = w0 + 542;
    const bool hasNext = (r + 1 < N_);   // row r+1 exists

    __shared__ float eRing[17][128];     // row 16 never written: zero boundary
    for (int i = tid; i < 17 * 128; i += 512) ((float*)eRing)[i] = 0.f;
    __syncthreads();

    const float2* Wb = g_w + (size_t)b * ND_ * N_;
    float*        Eb = g_e + (size_t)b * ND_ * N_;

    float*       ringWr = eRing[wid];
    const float* ringRd = eRing[wid + 1];   // warp 15 -> row 16 (zeros)

    const float2 zero2 = make_float2(0.f, 0.f);

    float2 qA[16], qB[16];
#pragma unroll
    for (int q = 0; q < 16; ++q) {
        const int dd = dTop + 1 - q;
        const bool ok = (dd <= ND_ - 1);
        qA[q] = ok ? Wb[(size_t)dd * N_ + r] : zero2;
        qB[q] = (ok && hasNext) ? Wb[(size_t)dd * N_ + r + 1] : zero2;
    }

    float2 bPrev = zero2;
    {
        const int dd = dTop + 2;
        if (dd <= ND_ - 1 && hasNext) bPrev = Wb[(size_t)dd * N_ + r + 1];
    }

    float ep      = 0.f;   // my E at d+1
    float nbEPrev = 0.f;   // neighbor E at d+2

    for (int c = 0; c < 17; ++c) {
        if (wid < 15) nbar_(wid + 1);         // wait producer through chunk c+1
        const int d0 = dTop - 32 * c;
#pragma unroll
        for (int s = 0; s < 32; ++s) {
            const int d = d0 - s;
            const float2 cA = qA[s & 15];    // W[d+1][r]
            const float2 cB = qB[s & 15];    // W[d+1][r+1]
            int dd = d - 15; dd = dd < 0 ? 0 : dd;
            qA[s & 15] = Wb[(size_t)dd * N_ + r];
            qB[s & 15] = hasNext ? Wb[(size_t)dd * N_ + r + 1] : zero2;

            const float rv = ringRd[(d + 1) & 127];     // broadcast LDS
            float nbE = __shfl_down_sync(0xffffffffu, ep, 1);
            nbE = (lane == 31) ? rv : nbE;

            float e = nbE * cB.x                          // E[i+1,j]   * wU
                    + ep  * cA.y                          // E[i,j+1]   * wL
                    + nbEPrev * (1.f - bPrev.x - bPrev.y);// E[i+1,j+1] * wD
            e = (d == 1022 && r == 511) ? 1.f : e;        // base case E[N,M]

            const bool active = (unsigned)(d - r) < (unsigned)M_;
            const float ev = active ? e : 0.f;
            Eb[(size_t)d * N_ + r] = ev;                  // unconditional STG
            ep = active ? e : ep;
            nbEPrev = nbE;
            bPrev = cB;
            if (lane == 0) ringWr[d & 127] = ep;          // @p STS.32
        }
        if (wid > 0 && c >= 1) nbar_(wid);    // signal: chunk c done
    }
    if (wid > 0) nbar_(wid);                  // extra phase (balance 17/17)
}

// ---------------------------------------------------------------------------
// launch
// ---------------------------------------------------------------------------
extern "C" void kernel_launch(void* const* d_in, const int* in_sizes, int n_in,
                              void* d_out, int out_size)
{
    const float* zx = (const float*)d_in[0];
    const float* zy = (const float*)d_in[1];
    const float* gx = (const float*)d_in[2];
    const float* gy = (const float*)d_in[3];
    float* out = (float*)d_out;   // [aln | theta | A]

    dim3 ggrid(M_ / 128, N_ / 128, 2 * B_);
    gemm_act_kernel<<<ggrid, 256>>>(zx, zy, gx, gy, out);

    dim3 tgrid(M_ / 32, N_ / 32, B_);
    diag_kernel<<<tgrid, 256>>>(out);
    nw_fwd_kernel<<<B_, 512>>>();
    nw_bwd_kernel<<<B_, 512>>>();
    undiag_kernel<<<tgrid, 256>>>(out);
}

// round 14
// speedup vs baseline: 1.1541x; 1.0348x over previous
#include <cuda_runtime.h>
#include <math.h>

constexpr int B_  = 8;
constexpr int N_  = 512;
constexpr int M_  = 512;
constexpr int D_  = 512;
constexpr int ND_ = N_ + M_ - 1;   // 1023 anti-diagonals
constexpr float NEGL    = -1.0e9f;
constexpr float INV_LN2 = 1.44269504088896340736f;

typedef unsigned long long ull;

// Diagonal-major scratch (zero-initialized; invalid slots are never written,
// so they stay zero — bwd relies on this for implicit masking).
__device__ float2 g_tha[(size_t)B_ * ND_ * N_];
__device__ float2 g_w  [(size_t)B_ * ND_ * N_];
__device__ float  g_e  [(size_t)B_ * ND_ * N_];

__device__ __forceinline__ float ex2f_(float x) { float y; asm("ex2.approx.ftz.f32 %0, %1;" : "=f"(y) : "f"(x)); return y; }
__device__ __forceinline__ float lg2f_(float x) { float y; asm("lg2.approx.f32 %0, %1;"     : "=f"(y) : "f"(x)); return y; }
__device__ __forceinline__ float rcpf_(float x) { float y; asm("rcp.approx.f32 %0, %1;"     : "=f"(y) : "f"(x)); return y; }

// packed dual-fp32 FMA (sm_103a FFMA2; PTX-only form)
__device__ __forceinline__ ull pack2_(float x) {
    ull r; const unsigned u = __float_as_uint(x);
    asm("mov.b64 %0, {%1, %1};" : "=l"(r) : "r"(u));
    return r;
}
__device__ __forceinline__ void ffma2_(ull& d, ull a, ull b) {
    asm("fma.rn.f32x2 %0, %1, %2, %0;" : "+l"(d) : "l"(a), "l"(b));
}

// named barrier, 64 threads (one producer warp + one consumer warp)
__device__ __forceinline__ void nbar_(int id) {
    asm volatile("bar.sync %0, 64;" :: "r"(id) : "memory");
}

// ---------------------------------------------------------------------------
// GEMM + activation via packed FFMA2: 128x128 tile, 256 thr, 8x8 micro tile
// (4 float2 pairs along n), K-chunks of 16. Same data path as the proven
// SIMT kernel; only the inner product uses fma.rn.f32x2.
// ---------------------------------------------------------------------------
__global__ void __launch_bounds__(256, 2) gemm_act_kernel(
    const float* __restrict__ zx, const float* __restrict__ zy,
    const float* __restrict__ gx, const float* __restrict__ gy,
    float* __restrict__ out)
{
    const int mz  = blockIdx.z;
    const int b   = mz & 7;
    const int sel = mz >> 3;
    const float* X = (sel ? gx : zx) + (size_t)b * N_ * D_;
    const float* Y = (sel ? gy : zy) + (size_t)b * M_ * D_;
    float* C = out + (size_t)(1 + sel) * B_ * N_ * M_ + (size_t)b * N_ * M_;

    const int row0 = blockIdx.y * 128;
    const int col0 = blockIdx.x * 128;

    __shared__ float Xs[16][132];
    __shared__ float Ys[16][132];

    const int t  = threadIdx.x;
    const int lr = t >> 1;
    const int lk = (t & 1) * 8;
    const int ty = t >> 4;
    const int tx = t & 15;

    ull acc2[8][4];
#pragma unroll
    for (int r = 0; r < 8; ++r)
#pragma unroll
        for (int c = 0; c < 4; ++c) acc2[r][c] = 0ull;

    for (int k0 = 0; k0 < D_; k0 += 16) {
        const float4 xv0 = *(const float4*)(X + (size_t)(row0 + lr) * D_ + k0 + lk);
        const float4 xv1 = *(const float4*)(X + (size_t)(row0 + lr) * D_ + k0 + lk + 4);
        const float4 yv0 = *(const float4*)(Y + (size_t)(col0 + lr) * D_ + k0 + lk);
        const float4 yv1 = *(const float4*)(Y + (size_t)(col0 + lr) * D_ + k0 + lk + 4);
        __syncthreads();
        Xs[lk + 0][lr] = xv0.x; Xs[lk + 1][lr] = xv0.y; Xs[lk + 2][lr] = xv0.z; Xs[lk + 3][lr] = xv0.w;
        Xs[lk + 4][lr] = xv1.x; Xs[lk + 5][lr] = xv1.y; Xs[lk + 6][lr] = xv1.z; Xs[lk + 7][lr] = xv1.w;
        Ys[lk + 0][lr] = yv0.x; Ys[lk + 1][lr] = yv0.y; Ys[lk + 2][lr] = yv0.z; Ys[lk + 3][lr] = yv0.w;
        Ys[lk + 4][lr] = yv1.x; Ys[lk + 5][lr] = yv1.y; Ys[lk + 6][lr] = yv1.z; Ys[lk + 7][lr] = yv1.w;
        __syncthreads();
#pragma unroll
        for (int kk = 0; kk < 16; ++kk) {
            float a0[8];
            *(float4*)(a0)     = *(const float4*)&Xs[kk][ty * 8];
            *(float4*)(a0 + 4) = *(const float4*)&Xs[kk][ty * 8 + 4];
            ull bp[4];
            {
                const ulonglong2 bv0 = *(const ulonglong2*)&Ys[kk][tx * 8];
                const ulonglong2 bv1 = *(const ulonglong2*)&Ys[kk][tx * 8 + 4];
                bp[0] = bv0.x; bp[1] = bv0.y; bp[2] = bv1.x; bp[3] = bv1.y;
            }
            ull ap[8];
#pragma unroll
            for (int r = 0; r < 8; ++r) ap[r] = pack2_(a0[r]);
#pragma unroll
            for (int r = 0; r < 8; ++r)
#pragma unroll
                for (int c = 0; c < 4; ++c)
                    ffma2_(acc2[r][c], ap[r], bp[c]);
        }
    }

    // epilogue + activation
#pragma unroll
    for (int r = 0; r < 8; ++r) {
        const int row = row0 + ty * 8 + r;
#pragma unroll
        for (int c4 = 0; c4 < 2; ++c4) {       // two float4 stores (4 pairs)
            float4 v;
            float* vp = &v.x;
#pragma unroll
            for (int p = 0; p < 2; ++p) {
                const ull a = acc2[r][c4 * 2 + p];
                unsigned lo, hi;
                asm("mov.b64 {%0, %1}, %2;" : "=r"(lo), "=r"(hi) : "l"(a));
                const float x0 = __uint_as_float(lo);
                const float x1 = __uint_as_float(hi);
                const float l0 = log1pf(__expf(-fabsf(x0)));
                const float l1 = log1pf(__expf(-fabsf(x1)));
                vp[p * 2 + 0] = sel ? (fminf(x0, 0.f) - l0) : (fmaxf(x0, 0.f) + l0);
                vp[p * 2 + 1] = sel ? (fminf(x1, 0.f) - l1) : (fmaxf(x1, 0.f) + l1);
            }
            *(float4*)(C + (size_t)row * M_ + col0 + tx * 8 + c4 * 4) = v;
        }
    }
}

// ---------------------------------------------------------------------------
// Diagonalize: theta,A (row-major) -> g_tha (diag-major float2, pre-scaled).
// ---------------------------------------------------------------------------
__global__ void __launch_bounds__(256) diag_kernel(const float* __restrict__ out)
{
    const float* theta = out + (size_t)B_ * N_ * M_;
    const float* Ag    = out + (size_t)2 * B_ * N_ * M_;
    const int b  = blockIdx.z;
    const int i0 = blockIdx.y * 32;
    const int j0 = blockIdx.x * 32;

    __shared__ float sth[32 * 32];
    __shared__ float sa [32 * 32];

    const int t    = threadIdx.x;
    const int warp = t >> 5;
    const int lane = t & 31;

#pragma unroll
    for (int it = 0; it < 4; ++it) {
        const int r = warp + it * 8;
        const int c = lane;
        const size_t g = ((size_t)b * N_ + (i0 + r)) * M_ + (j0 + c);
        sth[r * 32 + c] = theta[g] * INV_LN2;
        sa [r * 32 + c] = Ag[g]    * INV_LN2;
    }
    __syncthreads();

    float2* dst = g_tha + (size_t)b * ND_ * N_;
#pragma unroll
    for (int dd0 = 0; dd0 < 64; dd0 += 8) {
        const int dd = dd0 + warp;
        const int il = lane;
        const int jl = dd - il;
        if ((unsigned)jl < 32u) {
            const int d = i0 + j0 + dd;
            dst[(size_t)d * N_ + (i0 + il)] = make_float2(sth[il * 32 + jl], sa[il * 32 + jl]);
        }
    }
}

// ---------------------------------------------------------------------------
// Undiagonalize: g_e (diag-major) -> aln (row-major).
// ---------------------------------------------------------------------------
__global__ void __launch_bounds__(256) undiag_kernel(float* __restrict__ out)
{
    const int b  = blockIdx.z;
    const int i0 = blockIdx.y * 32;
    const int j0 = blockIdx.x * 32;

    __shared__ float se[32 * 32];

    const int t    = threadIdx.x;
    const int warp = t >> 5;
    const int lane = t & 31;

    const float* src = g_e + (size_t)b * ND_ * N_;
#pragma unroll
    for (int dd0 = 0; dd0 < 64; dd0 += 8) {
        const int dd = dd0 + warp;
        const int il = lane;
        const int jl = dd - il;
        if ((unsigned)jl < 32u) {
            const int d = i0 + j0 + dd;
            se[il * 32 + jl] = src[(size_t)d * N_ + (i0 + il)];
        }
    }
    __syncthreads();

    float* alnB = out + (size_t)b * N_ * M_;
#pragma unroll
    for (int it = 0; it < 4; ++it) {
        const int r = warp + it * 8;
        const int c = lane;
        alnB[(size_t)(i0 + r) * M_ + (j0 + c)] = se[r * 32 + c];
    }
}

// ---------------------------------------------------------------------------
// Forward soft-NW (R12 config, kept): pairwise named barriers decouple warps.
// ---------------------------------------------------------------------------
__global__ void __launch_bounds__(512) nw_fwd_kernel()
{
    const int b    = blockIdx.x;
    const int tid  = threadIdx.x;
    const int wid  = tid >> 5;
    const int lane = tid & 31;
    const int r    = tid;
    const int w0   = wid * 32;

    __shared__ float bndV[17][128];   // row 16 never written: NEGL boundary
    for (int i = tid; i < 17 * 128; i += 512) ((float*)bndV)[i] = NEGL;
    __syncthreads();

    const float2* THA = g_tha + (size_t)b * ND_ * N_;
    float2*       Wb  = g_w   + (size_t)b * ND_ * N_;

    float*       ringWr = bndV[wid];
    const float* ringRd = bndV[wid == 0 ? 16 : wid - 1];

    float2 th[16];
#pragma unroll
    for (int q = 0; q < 16; ++q) th[q] = THA[(size_t)(w0 + q) * N_ + r];

    float vp     = NEGL;
    float nbPrev = (tid == 0) ? 0.f : NEGL;   // seeds V[0,0] = 0 for cell (0,0)

    for (int c = 0; c < 17; ++c) {
        if (wid > 0) nbar_(wid);              // wait producer through chunk c+1
        const int d0 = w0 + 32 * c;
#pragma unroll
        for (int s = 0; s < 32; ++s) {
            const int d = d0 + s;
            const float2 ta = th[s & 15];
            int dp = d + 16; dp = dp > ND_ - 1 ? ND_ - 1 : dp;
            th[s & 15] = THA[(size_t)dp * N_ + r];

            const float ringv = ringRd[(d - 1) & 127];     // broadcast LDS
            float nb = __shfl_up_sync(0xffffffffu, vp, 1);
            nb = (lane == 0) ? ringv : nb;

            const float x0 = ta.y + nb;        // A + V[i-1, j]
            const float x2 = ta.y + vp;        // A + V[i,   j-1]
            const float dg = nbPrev;           //     V[i-1, j-1]
            const float m  = fmaxf(fmaxf(x0, x2), dg);
            const float e0 = ex2f_(x0 - m);
            const float e1 = ex2f_(dg - m);
            const float e2 = ex2f_(x2 - m);
            const float ss = e0 + e1 + e2;
            const float rr = rcpf_(ss);
            const float v  = ta.x + m + lg2f_(ss);

            const bool active = (unsigned)(d - r) < (unsigned)M_;
            if (active) Wb[(size_t)d * N_ + r] = make_float2(e0 * rr, e2 * rr);
            vp = active ? v : vp;
            nbPrev = nb;
            if (lane == 31) ringWr[d & 127] = vp;          // @p STS.32
        }
        if (wid < 15 && c >= 1) nbar_(wid + 1);   // signal: chunk c done
    }
    if (wid < 15) nbar_(wid + 1);                 // extra phase (balance 17/17)
}

// ---------------------------------------------------------------------------
// Backward soft-NW (R7/R9 config, reverted — measured 151.6us twice):
// off-chain weights via two depth-16 diag-major register streams; global
// barrier wavefront, 47 waves x 32 steps.
//   E[i,j] = E[i+1,j]*wU(i+1,j) + E[i,j+1]*wL(i,j+1) + E[i+1,j+1]*wD(i+1,j+1)
// ---------------------------------------------------------------------------
__global__ void __launch_bounds__(512) nw_bwd_kernel()
{
    const int b    = blockIdx.x;
    const int tid  = threadIdx.x;
    const int wid  = tid >> 5;
    const int lane = tid & 31;
    const int r    = tid;
    const int w0   = wid * 32;
    const int dTop = w0 + 542;
    const bool hasNext = (r + 1 < N_);   // row r+1 exists

    __shared__ float eRing[17][128];     // row 16 never written: zero boundary
    for (int i = tid; i < 17 * 128; i += 512) ((float*)eRing)[i] = 0.f;
    __syncthreads();

    const float2* Wb = g_w + (size_t)b * ND_ * N_;
    float*        Eb = g_e + (size_t)b * ND_ * N_;

    float*       ringWr = eRing[wid];
    const float* ringRd = eRing[wid + 1];   // warp 15 -> row 16 (zeros)

    const float2 zero2 = make_float2(0.f, 0.f);

    float2 qA[16], qB[16];
#pragma unroll
    for (int q = 0; q < 16; ++q) {
        const int dd = dTop + 1 - q;
        const bool ok = (dd <= ND_ - 1);
        qA[q] = ok ? Wb[(size_t)dd * N_ + r] : zero2;
        qB[q] = (ok && hasNext) ? Wb[(size_t)dd * N_ + r + 1] : zero2;
    }

    float2 bPrev = zero2;
    {
        const int dd = dTop + 2;
        if (dd <= ND_ - 1 && hasNext) bPrev = Wb[(size_t)dd * N_ + r + 1];
    }

    float ep      = 0.f;   // my E at d+1
    float nbEPrev = 0.f;   // neighbor E at d+2

    for (int t = 0; t < 47; ++t) {
        const int cc = t - 2 * (15 - wid);
        if (cc >= 0 && cc < 17) {
            const int d0 = dTop - 32 * cc;
#pragma unroll
            for (int s = 0; s < 32; ++s) {
                const int d = d0 - s;
                const float2 cA = qA[s & 15];    // W[d+1][r]
                const float2 cB = qB[s & 15];    // W[d+1][r+1]
                int dd = d - 15; dd = dd < 0 ? 0 : dd;
                qA[s & 15] = Wb[(size_t)dd * N_ + r];
                qB[s & 15] = hasNext ? Wb[(size_t)dd * N_ + r + 1] : zero2;

                const float rv = ringRd[(d + 1) & 127];     // broadcast LDS
                float nbE = __shfl_down_sync(0xffffffffu, ep, 1);
                nbE = (lane == 31) ? rv : nbE;

                float e = nbE * cB.x                          // E[i+1,j]   * wU
                        + ep  * cA.y                          // E[i,j+1]   * wL
                        + nbEPrev * (1.f - bPrev.x - bPrev.y);// E[i+1,j+1] * wD
                e = (d == 1022 && r == 511) ? 1.f : e;        // base case E[N,M]

                const bool active = (unsigned)(d - r) < (unsigned)M_;
                const float ev = active ? e : 0.f;
                Eb[(size_t)d * N_ + r] = ev;                  // unconditional STG
                ep = active ? e : ep;
                nbEPrev = nbE;
                bPrev = cB;
                if (lane == 0) ringWr[d & 127] = ep;          // @p STS.32
            }
        }
        __syncthreads();
    }
}

// ---------------------------------------------------------------------------
// launch
// ---------------------------------------------------------------------------
extern "C" void kernel_launch(void* const* d_in, const int* in_sizes, int n_in,
                              void* d_out, int out_size)
{
    const float* zx = (const float*)d_in[0];
    const float* zy = (const float*)d_in[1];
    const float* gx = (const float*)d_in[2];
    const float* gy = (const float*)d_in[3];
    float* out = (float*)d_out;   // [aln | theta | A]

    dim3 ggrid(M_ / 128, N_ / 128, 2 * B_);
    gemm_act_kernel<<<ggrid, 256>>>(zx, zy, gx, gy, out);

    dim3 tgrid(M_ / 32, N_ / 32, B_);
    diag_kernel<<<tgrid, 256>>>(out);
    nw_fwd_kernel<<<B_, 512>>>();
    nw_bwd_kernel<<<B_, 512>>>();
    undiag_kernel<<<tgrid, 256>>>(out);
}

// round 15
// speedup vs baseline: 1.1608x; 1.0058x over previous
#include <cuda_runtime.h>
#include <math.h>

constexpr int B_  = 8;
constexpr int N_  = 512;
constexpr int M_  = 512;
constexpr int D_  = 512;
constexpr int ND_ = N_ + M_ - 1;   // 1023 anti-diagonals
constexpr float NEGL    = -1.0e9f;
constexpr float INV_LN2 = 1.44269504088896340736f;

// Diagonal-major scratch (zero-initialized; invalid slots are never written,
// so they stay zero — bwd relies on this for implicit masking).
__device__ float2 g_tha[(size_t)B_ * ND_ * N_];
__device__ float2 g_w  [(size_t)B_ * ND_ * N_];
__device__ float  g_e  [(size_t)B_ * ND_ * N_];

__device__ __forceinline__ float ex2f_(float x) { float y; asm("ex2.approx.ftz.f32 %0, %1;" : "=f"(y) : "f"(x)); return y; }
__device__ __forceinline__ float lg2f_(float x) { float y; asm("lg2.approx.f32 %0, %1;"     : "=f"(y) : "f"(x)); return y; }
__device__ __forceinline__ float rcpf_(float x) { float y; asm("rcp.approx.f32 %0, %1;"     : "=f"(y) : "f"(x)); return y; }

// named barrier, 64 threads (one producer warp + one consumer warp)
__device__ __forceinline__ void nbar_(int id) {
    asm volatile("bar.sync %0, 64;" :: "r"(id) : "memory");
}

// ---------------------------------------------------------------------------
// GEMM + activation (R1 SIMT version, measured 120us — 95% of FFMA roofline):
// 128x128 tile, 256 thr, 8x8 micro tile, K-chunks of 16.
// ---------------------------------------------------------------------------
__global__ void __launch_bounds__(256, 2) gemm_act_kernel(
    const float* __restrict__ zx, const float* __restrict__ zy,
    const float* __restrict__ gx, const float* __restrict__ gy,
    float* __restrict__ out)
{
    const int mz  = blockIdx.z;
    const int b   = mz & 7;
    const int sel = mz >> 3;
    const float* X = (sel ? gx : zx) + (size_t)b * N_ * D_;
    const float* Y = (sel ? gy : zy) + (size_t)b * M_ * D_;
    float* C = out + (size_t)(1 + sel) * B_ * N_ * M_ + (size_t)b * N_ * M_;

    const int row0 = blockIdx.y * 128;
    const int col0 = blockIdx.x * 128;

    __shared__ float Xs[16][132];
    __shared__ float Ys[16][132];

    const int t  = threadIdx.x;
    const int lr = t >> 1;
    const int lk = (t & 1) * 8;
    const int ty = t >> 4;
    const int tx = t & 15;

    float acc[8][8];
#pragma unroll
    for (int r = 0; r < 8; ++r)
#pragma unroll
        for (int c = 0; c < 8; ++c) acc[r][c] = 0.f;

    for (int k0 = 0; k0 < D_; k0 += 16) {
        const float4 xv0 = *(const float4*)(X + (size_t)(row0 + lr) * D_ + k0 + lk);
        const float4 xv1 = *(const float4*)(X + (size_t)(row0 + lr) * D_ + k0 + lk + 4);
        const float4 yv0 = *(const float4*)(Y + (size_t)(col0 + lr) * D_ + k0 + lk);
        const float4 yv1 = *(const float4*)(Y + (size_t)(col0 + lr) * D_ + k0 + lk + 4);
        __syncthreads();
        Xs[lk + 0][lr] = xv0.x; Xs[lk + 1][lr] = xv0.y; Xs[lk + 2][lr] = xv0.z; Xs[lk + 3][lr] = xv0.w;
        Xs[lk + 4][lr] = xv1.x; Xs[lk + 5][lr] = xv1.y; Xs[lk + 6][lr] = xv1.z; Xs[lk + 7][lr] = xv1.w;
        Ys[lk + 0][lr] = yv0.x; Ys[lk + 1][lr] = yv0.y; Ys[lk + 2][lr] = yv0.z; Ys[lk + 3][lr] = yv0.w;
        Ys[lk + 4][lr] = yv1.x; Ys[lk + 5][lr] = yv1.y; Ys[lk + 6][lr] = yv1.z; Ys[lk + 7][lr] = yv1.w;
        __syncthreads();
#pragma unroll
        for (int kk = 0; kk < 16; ++kk) {
            float a0[8], b0[8];
            *(float4*)(a0)     = *(const float4*)&Xs[kk][ty * 8];
            *(float4*)(a0 + 4) = *(const float4*)&Xs[kk][ty * 8 + 4];
            *(float4*)(b0)     = *(const float4*)&Ys[kk][tx * 8];
            *(float4*)(b0 + 4) = *(const float4*)&Ys[kk][tx * 8 + 4];
#pragma unroll
            for (int r = 0; r < 8; ++r)
#pragma unroll
                for (int c = 0; c < 8; ++c)
                    acc[r][c] = fmaf(a0[r], b0[c], acc[r][c]);
        }
    }

#pragma unroll
    for (int r = 0; r < 8; ++r) {
        const int row = row0 + ty * 8 + r;
#pragma unroll
        for (int c4 = 0; c4 < 8; c4 += 4) {
            float4 v;
            float* vp = &v.x;
#pragma unroll
            for (int q = 0; q < 4; ++q) {
                const float x = acc[r][c4 + q];
                const float l = log1pf(__expf(-fabsf(x)));
                vp[q] = sel ? (fminf(x, 0.f) - l)     // log_sigmoid
                            : (fmaxf(x, 0.f) + l);    // softplus
            }
            *(float4*)(C + (size_t)row * M_ + col0 + tx * 8 + c4) = v;
        }
    }
}

// ---------------------------------------------------------------------------
// Diagonalize: theta,A (row-major) -> g_tha (diag-major float2, pre-scaled).
// ---------------------------------------------------------------------------
__global__ void __launch_bounds__(256) diag_kernel(const float* __restrict__ out)
{
    const float* theta = out + (size_t)B_ * N_ * M_;
    const float* Ag    = out + (size_t)2 * B_ * N_ * M_;
    const int b  = blockIdx.z;
    const int i0 = blockIdx.y * 32;
    const int j0 = blockIdx.x * 32;

    __shared__ float sth[32 * 32];
    __shared__ float sa [32 * 32];

    const int t    = threadIdx.x;
    const int warp = t >> 5;
    const int lane = t & 31;

#pragma unroll
    for (int it = 0; it < 4; ++it) {
        const int r = warp + it * 8;
        const int c = lane;
        const size_t g = ((size_t)b * N_ + (i0 + r)) * M_ + (j0 + c);
        sth[r * 32 + c] = theta[g] * INV_LN2;
        sa [r * 32 + c] = Ag[g]    * INV_LN2;
    }
    __syncthreads();

    float2* dst = g_tha + (size_t)b * ND_ * N_;
#pragma unroll
    for (int dd0 = 0; dd0 < 64; dd0 += 8) {
        const int dd = dd0 + warp;
        const int il = lane;
        const int jl = dd - il;
        if ((unsigned)jl < 32u) {
            const int d = i0 + j0 + dd;
            dst[(size_t)d * N_ + (i0 + il)] = make_float2(sth[il * 32 + jl], sa[il * 32 + jl]);
        }
    }
}

// ---------------------------------------------------------------------------
// Undiagonalize: g_e (diag-major) -> aln (row-major).
// ---------------------------------------------------------------------------
__global__ void __launch_bounds__(256) undiag_kernel(float* __restrict__ out)
{
    const int b  = blockIdx.z;
    const int i0 = blockIdx.y * 32;
    const int j0 = blockIdx.x * 32;

    __shared__ float se[32 * 32];

    const int t    = threadIdx.x;
    const int warp = t >> 5;
    const int lane = t & 31;

    const float* src = g_e + (size_t)b * ND_ * N_;
#pragma unroll
    for (int dd0 = 0; dd0 < 64; dd0 += 8) {
        const int dd = dd0 + warp;
        const int il = lane;
        const int jl = dd - il;
        if ((unsigned)jl < 32u) {
            const int d = i0 + j0 + dd;
            se[il * 32 + jl] = src[(size_t)d * N_ + (i0 + il)];
        }
    }
    __syncthreads();

    float* alnB = out + (size_t)b * N_ * M_;
#pragma unroll
    for (int it = 0; it < 4; ++it) {
        const int r = warp + it * 8;
        const int c = lane;
        alnB[(size_t)(i0 + r) * M_ + (j0 + c)] = se[r * 32 + c];
    }
}

// ---------------------------------------------------------------------------
// Forward soft-NW (R12 config, kept — the masked -24us win): pairwise named
// barriers decouple warps; R7 step body, depth-16 prefetch.
// ---------------------------------------------------------------------------
__global__ void __launch_bounds__(512) nw_fwd_kernel()
{
    const int b    = blockIdx.x;
    const int tid  = threadIdx.x;
    const int wid  = tid >> 5;
    const int lane = tid & 31;
    const int r    = tid;
    const int w0   = wid * 32;

    __shared__ float bndV[17][128];   // row 16 never written: NEGL boundary
    for (int i = tid; i < 17 * 128; i += 512) ((float*)bndV)[i] = NEGL;
    __syncthreads();

    const float2* THA = g_tha + (size_t)b * ND_ * N_;
    float2*       Wb  = g_w   + (size_t)b * ND_ * N_;

    float*       ringWr = bndV[wid];
    const float* ringRd = bndV[wid == 0 ? 16 : wid - 1];

    float2 th[16];
#pragma unroll
    for (int q = 0; q < 16; ++q) th[q] = THA[(size_t)(w0 + q) * N_ + r];

    float vp     = NEGL;
    float nbPrev = (tid == 0) ? 0.f : NEGL;   // seeds V[0,0] = 0 for cell (0,0)

    for (int c = 0; c < 17; ++c) {
        if (wid > 0) nbar_(wid);              // wait producer through chunk c+1
        const int d0 = w0 + 32 * c;
#pragma unroll
        for (int s = 0; s < 32; ++s) {
            const int d = d0 + s;
            const float2 ta = th[s & 15];
            int dp = d + 16; dp = dp > ND_ - 1 ? ND_ - 1 : dp;
            th[s & 15] = THA[(size_t)dp * N_ + r];

            const float ringv = ringRd[(d - 1) & 127];     // broadcast LDS
            float nb = __shfl_up_sync(0xffffffffu, vp, 1);
            nb = (lane == 0) ? ringv : nb;

            const float x0 = ta.y + nb;        // A + V[i-1, j]
            const float x2 = ta.y + vp;        // A + V[i,   j-1]
            const float dg = nbPrev;           //     V[i-1, j-1]
            const float m  = fmaxf(fmaxf(x0, x2), dg);
            const float e0 = ex2f_(x0 - m);
            const float e1 = ex2f_(dg - m);
            const float e2 = ex2f_(x2 - m);
            const float ss = e0 + e1 + e2;
            const float rr = rcpf_(ss);
            const float v  = ta.x + m + lg2f_(ss);

            const bool active = (unsigned)(d - r) < (unsigned)M_;
            if (active) Wb[(size_t)d * N_ + r] = make_float2(e0 * rr, e2 * rr);
            vp = active ? v : vp;
            nbPrev = nb;
            if (lane == 31) ringWr[d & 127] = vp;          // @p STS.32
        }
        if (wid < 15 && c >= 1) nbar_(wid + 1);   // signal: chunk c done
    }
    if (wid < 15) nbar_(wid + 1);                 // extra phase (balance 17/17)
}

// ---------------------------------------------------------------------------
// Backward soft-NW (R7/R9 config — measured 151.6/152.4/152.7us):
// off-chain weights via two depth-16 diag-major register streams; global
// barrier wavefront, 47 waves x 32 steps.
//   E[i,j] = E[i+1,j]*wU(i+1,j) + E[i,j+1]*wL(i,j+1) + E[i+1,j+1]*wD(i+1,j+1)
// ---------------------------------------------------------------------------
__global__ void __launch_bounds__(512) nw_bwd_kernel()
{
    const int b    = blockIdx.x;
    const int tid  = threadIdx.x;
    const int wid  = tid >> 5;
    const int lane = tid & 31;
    const int r    = tid;
    const int w0   = wid * 32;
    const int dTop = w0 + 542;
    const bool hasNext = (r + 1 < N_);   // row r+1 exists

    __shared__ float eRing[17][128];     // row 16 never written: zero boundary
    for (int i = tid; i < 17 * 128; i += 512) ((float*)eRing)[i] = 0.f;
    __syncthreads();

    const float2* Wb = g_w + (size_t)b * ND_ * N_;
    float*        Eb = g_e + (size_t)b * ND_ * N_;

    float*       ringWr = eRing[wid];
    const float* ringRd = eRing[wid + 1];   // warp 15 -> row 16 (zeros)

    const float2 zero2 = make_float2(0.f, 0.f);

    float2 qA[16], qB[16];
#pragma unroll
    for (int q = 0; q < 16; ++q) {
        const int dd = dTop + 1 - q;
        const bool ok = (dd <= ND_ - 1);
        qA[q] = ok ? Wb[(size_t)dd * N_ + r] : zero2;
        qB[q] = (ok && hasNext) ? Wb[(size_t)dd * N_ + r + 1] : zero2;
    }

    float2 bPrev = zero2;
    {
        const int dd = dTop + 2;
        if (dd <= ND_ - 1 && hasNext) bPrev = Wb[(size_t)dd * N_ + r + 1];
    }

    float ep      = 0.f;   // my E at d+1
    float nbEPrev = 0.f;   // neighbor E at d+2

    for (int t = 0; t < 47; ++t) {
        const int cc = t - 2 * (15 - wid);
        if (cc >= 0 && cc < 17) {
            const int d0 = dTop - 32 * cc;
#pragma unroll
            for (int s = 0; s < 32; ++s) {
                const int d = d0 - s;
                const float2 cA = qA[s & 15];    // W[d+1][r]
                const float2 cB = qB[s & 15];    // W[d+1][r+1]
                int dd = d - 15; dd = dd < 0 ? 0 : dd;
                qA[s & 15] = Wb[(size_t)dd * N_ + r];
                qB[s & 15] = hasNext ? Wb[(size_t)dd * N_ + r + 1] : zero2;

                const float rv = ringRd[(d + 1) & 127];     // broadcast LDS
                float nbE = __shfl_down_sync(0xffffffffu, ep, 1);
                nbE = (lane == 31) ? rv : nbE;

                float e = nbE * cB.x                          // E[i+1,j]   * wU
                        + ep  * cA.y                          // E[i,j+1]   * wL
                        + nbEPrev * (1.f - bPrev.x - bPrev.y);// E[i+1,j+1] * wD
                e = (d == 1022 && r == 511) ? 1.f : e;        // base case E[N,M]

                const bool active = (unsigned)(d - r) < (unsigned)M_;
                const float ev = active ? e : 0.f;
                Eb[(size_t)d * N_ + r] = ev;                  // unconditional STG
                ep = active ? e : ep;
                nbEPrev = nbE;
                bPrev = cB;
                if (lane == 0) ringWr[d & 127] = ep;          // @p STS.32
            }
        }
        __syncthreads();
    }
}

// ---------------------------------------------------------------------------
// launch
// ---------------------------------------------------------------------------
extern "C" void kernel_launch(void* const* d_in, const int* in_sizes, int n_in,
                              void* d_out, int out_size)
{
    const float* zx = (const float*)d_in[0];
    const float* zy = (const float*)d_in[1];
    const float* gx = (const float*)d_in[2];
    const float* gy = (const float*)d_in[3];
    float* out = (float*)d_out;   // [aln | theta | A]

    dim3 ggrid(M_ / 128, N_ / 128, 2 * B_);
    gemm_act_kernel<<<ggrid, 256>>>(zx, zy, gx, gy, out);

    dim3 tgrid(M_ / 32, N_ / 32, B_);
    diag_kernel<<<tgrid, 256>>>(out);
    nw_fwd_kernel<<<B_, 512>>>();
    nw_bwd_kernel<<<B_, 512>>>();
    undiag_kernel<<<tgrid, 256>>>(out);
}

// round 17
// speedup vs baseline: 1.1782x; 1.0149x over previous
#include <cuda_runtime.h>
#include <math.h>

constexpr int B_  = 8;
constexpr int N_  = 512;
constexpr int M_  = 512;
constexpr int D_  = 512;
constexpr int ND_ = N_ + M_ - 1;   // 1023 anti-diagonals
constexpr float NEGL    = -1.0e9f;
constexpr float INV_LN2 = 1.44269504088896340736f;

// Diagonal-major scratch (zero-initialized; invalid slots are never written,
// so they stay zero — bwd relies on this for implicit masking).
__device__ float2 g_tha[(size_t)B_ * ND_ * N_];
__device__ float2 g_w  [(size_t)B_ * ND_ * N_];
__device__ float  g_e  [(size_t)B_ * ND_ * N_];

__device__ __forceinline__ float ex2f_(float x) { float y; asm("ex2.approx.ftz.f32 %0, %1;" : "=f"(y) : "f"(x)); return y; }
__device__ __forceinline__ float lg2f_(float x) { float y; asm("lg2.approx.f32 %0, %1;"     : "=f"(y) : "f"(x)); return y; }
__device__ __forceinline__ float rcpf_(float x) { float y; asm("rcp.approx.f32 %0, %1;"     : "=f"(y) : "f"(x)); return y; }

// named barrier, 64 threads (one producer warp + one consumer warp)
__device__ __forceinline__ void nbar_(int id) {
    asm volatile("bar.sync %0, 64;" :: "r"(id) : "memory");
}

// ---------------------------------------------------------------------------
// GEMM + activation: 128x128 tile, 256 thr, 8x8 micro tile, K-chunks of 16,
// DOUBLE-BUFFERED smem (one __syncthreads per chunk; LDG overlaps compute).
// ---------------------------------------------------------------------------
__global__ void __launch_bounds__(256, 2) gemm_act_kernel(
    const float* __restrict__ zx, const float* __restrict__ zy,
    const float* __restrict__ gx, const float* __restrict__ gy,
    float* __restrict__ out)
{
    const int mz  = blockIdx.z;
    const int b   = mz & 7;
    const int sel = mz >> 3;
    const float* X = (sel ? gx : zx) + (size_t)b * N_ * D_;
    const float* Y = (sel ? gy : zy) + (size_t)b * M_ * D_;
    float* C = out + (size_t)(1 + sel) * B_ * N_ * M_ + (size_t)b * N_ * M_;

    const int row0 = blockIdx.y * 128;
    const int col0 = blockIdx.x * 128;

    __shared__ float Xs[2][16][132];
    __shared__ float Ys[2][16][132];

    const int t  = threadIdx.x;
    const int lr = t >> 1;
    const int lk = (t & 1) * 8;
    const int ty = t >> 4;
    const int tx = t & 15;

    const float* Xp = X + (size_t)(row0 + lr) * D_ + lk;
    const float* Yp = Y + (size_t)(col0 + lr) * D_ + lk;

    float acc[8][8];
#pragma unroll
    for (int r = 0; r < 8; ++r)
#pragma unroll
        for (int c = 0; c < 8; ++c) acc[r][c] = 0.f;

    // prologue: load chunk 0
    float4 xv0 = *(const float4*)(Xp + 0);
    float4 xv1 = *(const float4*)(Xp + 4);
    float4 yv0 = *(const float4*)(Yp + 0);
    float4 yv1 = *(const float4*)(Yp + 4);

    for (int ck = 0; ck < 32; ++ck) {
        const int p = ck & 1;
        Xs[p][lk + 0][lr] = xv0.x; Xs[p][lk + 1][lr] = xv0.y; Xs[p][lk + 2][lr] = xv0.z; Xs[p][lk + 3][lr] = xv0.w;
        Xs[p][lk + 4][lr] = xv1.x; Xs[p][lk + 5][lr] = xv1.y; Xs[p][lk + 6][lr] = xv1.z; Xs[p][lk + 7][lr] = xv1.w;
        Ys[p][lk + 0][lr] = yv0.x; Ys[p][lk + 1][lr] = yv0.y; Ys[p][lk + 2][lr] = yv0.z; Ys[p][lk + 3][lr] = yv0.w;
        Ys[p][lk + 4][lr] = yv1.x; Ys[p][lk + 5][lr] = yv1.y; Ys[p][lk + 6][lr] = yv1.z; Ys[p][lk + 7][lr] = yv1.w;
        __syncthreads();

        if (ck < 31) {              // prefetch next chunk (overlaps compute)
            const int kn = (ck + 1) * 16;
            xv0 = *(const float4*)(Xp + kn);
            xv1 = *(const float4*)(Xp + kn + 4);
            yv0 = *(const float4*)(Yp + kn);
            yv1 = *(const float4*)(Yp + kn + 4);
        }

#pragma unroll
        for (int kk = 0; kk < 16; ++kk) {
            float a0[8], b0[8];
            *(float4*)(a0)     = *(const float4*)&Xs[p][kk][ty * 8];
            *(float4*)(a0 + 4) = *(const float4*)&Xs[p][kk][ty * 8 + 4];
            *(float4*)(b0)     = *(const float4*)&Ys[p][kk][tx * 8];
            *(float4*)(b0 + 4) = *(const float4*)&Ys[p][kk][tx * 8 + 4];
#pragma unroll
            for (int r = 0; r < 8; ++r)
#pragma unroll
                for (int c = 0; c < 8; ++c)
                    acc[r][c] = fmaf(a0[r], b0[c], acc[r][c]);
        }
    }

#pragma unroll
    for (int r = 0; r < 8; ++r) {
        const int row = row0 + ty * 8 + r;
#pragma unroll
        for (int c4 = 0; c4 < 8; c4 += 4) {
            float4 v;
            float* vp = &v.x;
#pragma unroll
            for (int q = 0; q < 4; ++q) {
                const float x = acc[r][c4 + q];
                const float l = log1pf(__expf(-fabsf(x)));
                vp[q] = sel ? (fminf(x, 0.f) - l)     // log_sigmoid
                            : (fmaxf(x, 0.f) + l);    // softplus
            }
            *(float4*)(C + (size_t)row * M_ + col0 + tx * 8 + c4) = v;
        }
    }
}

// ---------------------------------------------------------------------------
// Diagonalize: theta,A (row-major) -> g_tha (diag-major float2, pre-scaled).
// ---------------------------------------------------------------------------
__global__ void __launch_bounds__(256) diag_kernel(const float* __restrict__ out)
{
    const float* theta = out + (size_t)B_ * N_ * M_;
    const float* Ag    = out + (size_t)2 * B_ * N_ * M_;
    const int b  = blockIdx.z;
    const int i0 = blockIdx.y * 32;
    const int j0 = blockIdx.x * 32;

    __shared__ float sth[32 * 32];
    __shared__ float sa [32 * 32];

    const int t    = threadIdx.x;
    const int warp = t >> 5;
    const int lane = t & 31;

#pragma unroll
    for (int it = 0; it < 4; ++it) {
        const int r = warp + it * 8;
        const int c = lane;
        const size_t g = ((size_t)b * N_ + (i0 + r)) * M_ + (j0 + c);
        sth[r * 32 + c] = theta[g] * INV_LN2;
        sa [r * 32 + c] = Ag[g]    * INV_LN2;
    }
    __syncthreads();

    float2* dst = g_tha + (size_t)b * ND_ * N_;
#pragma unroll
    for (int dd0 = 0; dd0 < 64; dd0 += 8) {
        const int dd = dd0 + warp;
        const int il = lane;
        const int jl = dd - il;
        if ((unsigned)jl < 32u) {
            const int d = i0 + j0 + dd;
            dst[(size_t)d * N_ + (i0 + il)] = make_float2(sth[il * 32 + jl], sa[il * 32 + jl]);
        }
    }
}

// ---------------------------------------------------------------------------
// Undiagonalize: g_e (diag-major) -> aln (row-major).
// ---------------------------------------------------------------------------
__global__ void __launch_bounds__(256) undiag_kernel(float* __restrict__ out)
{
    const int b  = blockIdx.z;
    const int i0 = blockIdx.y * 32;
    const int j0 = blockIdx.x * 32;

    __shared__ float se[32 * 32];

    const int t    = threadIdx.x;
    const int warp = t >> 5;
    const int lane = t & 31;

    const float* src = g_e + (size_t)b * ND_ * N_;
#pragma unroll
    for (int dd0 = 0; dd0 < 64; dd0 += 8) {
        const int dd = dd0 + warp;
        const int il = lane;
        const int jl = dd - il;
        if ((unsigned)jl < 32u) {
            const int d = i0 + j0 + dd;
            se[il * 32 + jl] = src[(size_t)d * N_ + (i0 + il)];
        }
    }
    __syncthreads();

    float* alnB = out + (size_t)b * N_ * M_;
#pragma unroll
    for (int it = 0; it < 4; ++it) {
        const int r = warp + it * 8;
        const int c = lane;
        alnB[(size_t)(i0 + r) * M_ + (j0 + c)] = se[r * 32 + c];
    }
}

// ---------------------------------------------------------------------------
// Forward soft-NW (R12 config): pairwise named barriers decouple warps;
// R7 step body, depth-16 prefetch.
// ---------------------------------------------------------------------------
__global__ void __launch_bounds__(512) nw_fwd_kernel()
{
    const int b    = blockIdx.x;
    const int tid  = threadIdx.x;
    const int wid  = tid >> 5;
    const int lane = tid & 31;
    const int r    = tid;
    const int w0   = wid * 32;

    __shared__ float bndV[17][128];   // row 16 never written: NEGL boundary
    for (int i = tid; i < 17 * 128; i += 512) ((float*)bndV)[i] = NEGL;
    __syncthreads();

    const float2* THA = g_tha + (size_t)b * ND_ * N_;
    float2*       Wb  = g_w   + (size_t)b * ND_ * N_;

    float*       ringWr = bndV[wid];
    const float* ringRd = bndV[wid == 0 ? 16 : wid - 1];

    float2 th[16];
#pragma unroll
    for (int q = 0; q < 16; ++q) th[q] = THA[(size_t)(w0 + q) * N_ + r];

    float vp     = NEGL;
    float nbPrev = (tid == 0) ? 0.f : NEGL;   // seeds V[0,0] = 0 for cell (0,0)

    for (int c = 0; c < 17; ++c) {
        if (wid > 0) nbar_(wid);              // wait producer through chunk c+1
        const int d0 = w0 + 32 * c;
#pragma unroll
        for (int s = 0; s < 32; ++s) {
            const int d = d0 + s;
            const float2 ta = th[s & 15];
            int dp = d + 16; dp = dp > ND_ - 1 ? ND_ - 1 : dp;
            th[s & 15] = THA[(size_t)dp * N_ + r];

            const float ringv = ringRd[(d - 1) & 127];     // broadcast LDS
            float nb = __shfl_up_sync(0xffffffffu, vp, 1);
            nb = (lane == 0) ? ringv : nb;

            const float x0 = ta.y + nb;        // A + V[i-1, j]
            const float x2 = ta.y + vp;        // A + V[i,   j-1]
            const float dg = nbPrev;           //     V[i-1, j-1]
            const float m  = fmaxf(fmaxf(x0, x2), dg);
            const float e0 = ex2f_(x0 - m);
            const float e1 = ex2f_(dg - m);
            const float e2 = ex2f_(x2 - m);
            const float ss = e0 + e1 + e2;
            const float rr = rcpf_(ss);
            const float v  = ta.x + m + lg2f_(ss);

            const bool active = (unsigned)(d - r) < (unsigned)M_;
            if (active) Wb[(size_t)d * N_ + r] = make_float2(e0 * rr, e2 * rr);
            vp = active ? v : vp;
            nbPrev = nb;
            if (lane == 31) ringWr[d & 127] = vp;          // @p STS.32
        }
        if (wid < 15 && c >= 1) nbar_(wid + 1);   // signal: chunk c done
    }
    if (wid < 15) nbar_(wid + 1);                 // extra phase (balance 17/17)
}

// ---------------------------------------------------------------------------
// Backward soft-NW (R7/R9 config — measured 151.6/152.4/152.7/153.5us):
// off-chain weights via two depth-16 diag-major register streams; global
// barrier wavefront, 47 waves x 32 steps.
//   E[i,j] = E[i+1,j]*wU(i+1,j) + E[i,j+1]*wL(i,j+1) + E[i+1,j+1]*wD(i+1,j+1)
// ---------------------------------------------------------------------------
__global__ void __launch_bounds__(512) nw_bwd_kernel()
{
    const int b    = blockIdx.x;
    const int tid  = threadIdx.x;
    const int wid  = tid >> 5;
    const int lane = tid & 31;
    const int r    = tid;
    const int w0   = wid * 32;
    const int dTop = w0 + 542;
    const bool hasNext = (r + 1 < N_);   // row r+1 exists

    __shared__ float eRing[17][128];     // row 16 never written: zero boundary
    for (int i = tid; i < 17 * 128; i += 512) ((float*)eRing)[i] = 0.f;
    __syncthreads();

    const float2* Wb = g_w + (size_t)b * ND_ * N_;
    float*        Eb = g_e + (size_t)b * ND_ * N_;

    float*       ringWr = eRing[wid];
    const float* ringRd = eRing[wid + 1];   // warp 15 -> row 16 (zeros)

    const float2 zero2 = make_float2(0.f, 0.f);

    float2 qA[16], qB[16];
#pragma unroll
    for (int q = 0; q < 16; ++q) {
        const int dd = dTop + 1 - q;
        const bool ok = (dd <= ND_ - 1);
        qA[q] = ok ? Wb[(size_t)dd * N_ + r] : zero2;
        qB[q] = (ok && hasNext) ? Wb[(size_t)dd * N_ + r + 1] : zero2;
    }

    float2 bPrev = zero2;
    {
        const int dd = dTop + 2;
        if (dd <= ND_ - 1 && hasNext) bPrev = Wb[(size_t)dd * N_ + r + 1];
    }

    float ep      = 0.f;   // my E at d+1
    float nbEPrev = 0.f;   // neighbor E at d+2

    for (int t = 0; t < 47; ++t) {
        const int cc = t - 2 * (15 - wid);
        if (cc >= 0 && cc < 17) {
            const int d0 = dTop - 32 * cc;
#pragma unroll
            for (int s = 0; s < 32; ++s) {
                const int d = d0 - s;
                const float2 cA = qA[s & 15];    // W[d+1][r]
                const float2 cB = qB[s & 15];    // W[d+1][r+1]
                int dd = d - 15; dd = dd < 0 ? 0 : dd;
                qA[s & 15] = Wb[(size_t)dd * N_ + r];
                qB[s & 15] = hasNext ? Wb[(size_t)dd * N_ + r + 1] : zero2;

                const float rv = ringRd[(d + 1) & 127];     // broadcast LDS
                float nbE = __shfl_down_sync(0xffffffffu, ep, 1);
                nbE = (lane == 31) ? rv : nbE;

                float e = nbE * cB.x                          // E[i+1,j]   * wU
                        + ep  * cA.y                          // E[i,j+1]   * wL
                        + nbEPrev * (1.f - bPrev.x - bPrev.y);// E[i+1,j+1] * wD
                e = (d == 1022 && r == 511) ? 1.f : e;        // base case E[N,M]

                const bool active = (unsigned)(d - r) < (unsigned)M_;
                const float ev = active ? e : 0.f;
                Eb[(size_t)d * N_ + r] = ev;                  // unconditional STG
                ep = active ? e : ep;
                nbEPrev = nbE;
                bPrev = cB;
                if (lane == 0) ringWr[d & 127] = ep;          // @p STS.32
            }
        }
        __syncthreads();
    }
}

// ---------------------------------------------------------------------------
// launch
// ---------------------------------------------------------------------------
extern "C" void kernel_launch(void* const* d_in, const int* in_sizes, int n_in,
                              void* d_out, int out_size)
{
    const float* zx = (const float*)d_in[0];
    const float* zy = (const float*)d_in[1];
    const float* gx = (const float*)d_in[2];
    const float* gy = (const float*)d_in[3];
    float* out = (float*)d_out;   // [aln | theta | A]

    dim3 ggrid(M_ / 128, N_ / 128, 2 * B_);
    gemm_act_kernel<<<ggrid, 256>>>(zx, zy, gx, gy, out);

    dim3 tgrid(M_ / 32, N_ / 32, B_);
    diag_kernel<<<tgrid, 256>>>(out);
    nw_fwd_kernel<<<B_, 512>>>();
    nw_bwd_kernel<<<B_, 512>>>();
    undiag_kernel<<<tgrid, 256>>>(out);
}